// round 16
// baseline (speedup 1.0000x reference)
#include <cuda_runtime.h>
#include <math.h>
#include <stdint.h>

#define BSZ 512
#define ZD  256
#define REC_BLOCKS 512
#define TI 8                    // i-values per pm block (4 f32x2 pairs)
#define JCHUNKS 8
#define JC (BSZ / JCHUNKS)      // 64
#define NGEMM 64                // mma.sync gemm blocks (8 i-tiles x 8 j-tiles)
#define LOG2PI_F 1.8378770664093453f
#define LOG2E_F  1.4426950408889634f

// gemm smem: A[64][40] bf16 + B[64][40] bf16 (40 = 32 + 8 pad; 80B rows, 16B-mult)
#define GROW 40
#define ATILE_B (64 * GROW * 2)      // 5120
#define SMEM_SZ (2 * ATILE_B)        // 10240

typedef unsigned long long u64;

// ---------------- scratch ----------------------------------------------------
__device__ float g_Crow[BSZ];
__device__ float g_dwkl[BSZ];
__device__ float g_recb[REC_BLOCKS];
__device__ float g_tc[BSZ];
__device__ unsigned int g_ctr;               // zero-init; epi resets it each run
__device__ float g_M0[BSZ * BSZ];            // GEMM result (1MB, single slab)
__device__ float g_S[JCHUNKS][BSZ * ZD];     // pm partial sums (4MB)

// ---------------- packed helpers ----------------------------------------------
__device__ __forceinline__ u64 pk2(float lo, float hi) {
    u64 r; asm("mov.b64 %0,{%1,%2};" : "=l"(r) : "f"(lo), "f"(hi)); return r;
}
__device__ __forceinline__ void upk2(u64 v, float& lo, float& hi) {
    asm("mov.b64 {%0,%1},%2;" : "=f"(lo), "=f"(hi) : "l"(v));
}
__device__ __forceinline__ u64 fma2(u64 a, u64 b, u64 c) {
    u64 d; asm("fma.rn.f32x2 %0,%1,%2,%3;" : "=l"(d) : "l"(a), "l"(b), "l"(c)); return d;
}
__device__ __forceinline__ u64 add2(u64 a, u64 b) {
    u64 d; asm("add.rn.f32x2 %0,%1,%2;" : "=l"(d) : "l"(a), "l"(b)); return d;
}
__device__ __forceinline__ u64 mul2(u64 a, u64 b) {
    u64 d; asm("mul.rn.f32x2 %0,%1,%2;" : "=l"(d) : "l"(a), "l"(b)); return d;
}
__device__ __forceinline__ uint32_t exp2_to_f16x2(u64 x) {
    float xlo, xhi;
    upk2(x, xlo, xhi);
    uint32_t hx, he;
    asm("cvt.rn.f16x2.f32 %0,%1,%2;" : "=r"(hx) : "f"(xhi), "f"(xlo));
    asm("ex2.approx.f16x2 %0,%1;" : "=r"(he) : "r"(hx));
    return he;
}
__device__ __forceinline__ uint32_t hadd2(uint32_t a, uint32_t b) {
    uint32_t d; asm("add.rn.f16x2 %0,%1,%2;" : "=r"(d) : "r"(a), "r"(b)); return d;
}
__device__ __forceinline__ u64 f16x2_to_f32x2(uint32_t h) {
    float lo, hi;
    asm("{\n\t.reg .f16 l,h;\n\tmov.b32 {l,h},%2;\n\t"
        "cvt.f32.f16 %0,l;\n\tcvt.f32.f16 %1,h;\n\t}"
        : "=f"(lo), "=f"(hi) : "r"(h));
    return pk2(lo, hi);
}
__device__ __forceinline__ uint32_t bf16x2_pack(float lo, float hi) {
    uint32_t r; asm("cvt.rn.bf16x2.f32 %0,%1,%2;" : "=r"(r) : "f"(hi), "f"(lo)); return r;
}
__device__ __forceinline__ uint32_t smem_to_u32(const void* p) {
    uint32_t a;
    asm("{ .reg .u64 t; cvta.to.shared.u64 t, %1; cvt.u32.u64 %0, t; }"
        : "=r"(a) : "l"(p));
    return a;
}

// packed exp2 via FMA-pipe polynomial (deg-5, rel err ~2.4e-6); x <= ~0
__device__ __forceinline__ u64 exp2_poly2(u64 x) {
    const u64 MAGIC2  = pk2( 12582912.0f,  12582912.0f);
    const u64 NMAGIC2 = pk2(-12582912.0f, -12582912.0f);
    const u64 NEG1    = pk2(-1.0f, -1.0f);
    const u64 C0 = pk2(1.0f, 1.0f);
    const u64 C1 = pk2(0.69314718f,  0.69314718f);
    const u64 C2 = pk2(0.24022650f,  0.24022650f);
    const u64 C3 = pk2(0.055504110f, 0.055504110f);
    const u64 C4 = pk2(0.0096181291f, 0.0096181291f);
    const u64 C5 = pk2(0.0013333558f, 0.0013333558f);
    u64 tt = add2(x, MAGIC2);
    u64 tm = add2(tt, NMAGIC2);
    u64 r  = fma2(tm, NEG1, x);
    u64 rr = mul2(r, r);
    u64 A  = fma2(r, C1, C0);
    u64 B  = fma2(r, C3, C2);
    u64 Cc = fma2(r, C5, C4);
    u64 D  = fma2(rr, Cc, B);
    u64 E  = fma2(rr, D, A);               // 2^frac
    int tlo = (int)tt;
    int thi = (int)(tt >> 32);
    float nlo = __int_as_float((tlo << 23) + 0x3F800000);   // 2^n
    float nhi = __int_as_float((thi << 23) + 0x3F800000);
    return mul2(E, pk2(nlo, nhi));
}

// ---------------- mma.sync helpers (sm_80-era PTX; compute_103-safe) -----------
__device__ __forceinline__ void ldmx4(uint32_t* r, uint32_t addr) {
    asm volatile("ldmatrix.sync.aligned.m8n8.x4.shared.b16 {%0,%1,%2,%3}, [%4];"
        : "=r"(r[0]), "=r"(r[1]), "=r"(r[2]), "=r"(r[3]) : "r"(addr));
}
__device__ __forceinline__ void mma_bf16(float* d, const uint32_t* a,
                                         const uint32_t* b) {
    asm volatile("mma.sync.aligned.m16n8k16.row.col.f32.bf16.bf16.f32 "
        "{%0,%1,%2,%3}, {%4,%5,%6,%7}, {%8,%9}, {%0,%1,%2,%3};"
        : "+f"(d[0]), "+f"(d[1]), "+f"(d[2]), "+f"(d[3])
        : "r"(a[0]), "r"(a[1]), "r"(a[2]), "r"(a[3]), "r"(b[0]), "r"(b[1]));
}

// ---------------- reductions --------------------------------------------------
__device__ __forceinline__ float warp_sum(float v) {
#pragma unroll
    for (int o = 16; o; o >>= 1) v += __shfl_xor_sync(0xffffffffu, v, o);
    return v;
}
__device__ __forceinline__ float warp_max(float v) {
#pragma unroll
    for (int o = 16; o; o >>= 1) v = fmaxf(v, __shfl_xor_sync(0xffffffffu, v, o));
    return v;
}
__device__ __forceinline__ float block_sum_256(float v, float* sh) {
    int lane = threadIdx.x & 31, w = threadIdx.x >> 5;
    v = warp_sum(v);
    if (lane == 0) sh[w] = v;
    __syncthreads();
    float r = (threadIdx.x < 8) ? sh[threadIdx.x] : 0.0f;
    if (w == 0) r = warp_sum(r);
    __syncthreads();
    return r;
}
__device__ __forceinline__ float block_sum_512(float v, float* sh) {
    int lane = threadIdx.x & 31, w = threadIdx.x >> 5;
    v = warp_sum(v);
    if (lane == 0) sh[w] = v;
    __syncthreads();
    float r = (threadIdx.x < 16) ? sh[threadIdx.x] : 0.0f;
    if (w == 0) r = warp_sum(r);
    __syncthreads();
    return r;
}
__device__ __forceinline__ float block_max_512(float v, float* sh) {
    int lane = threadIdx.x & 31, w = threadIdx.x >> 5;
    v = warp_max(v);
    if (lane == 0) sh[w] = v;
    __syncthreads();
    float r = (threadIdx.x < 16) ? sh[threadIdx.x] : -INFINITY;
    if (w == 0) r = warp_max(r);
    __syncthreads();
    return r;
}

// ---------------- FMA-pipe natural log -----------------------------------------
__device__ __forceinline__ float fast_log(float x) {
    int ix = __float_as_int(x);
    int e  = (ix - 0x3f3504f3) >> 23;
    float m = __int_as_float(ix - (e << 23));
    float f = m - 1.0f;
    float z = f * f;
    float y = 7.0376836292e-2f;
    y = fmaf(y, f, -1.1514610310e-1f);
    y = fmaf(y, f,  1.1676998740e-1f);
    y = fmaf(y, f, -1.2420140846e-1f);
    y = fmaf(y, f,  1.4249322787e-1f);
    y = fmaf(y, f, -1.6668057665e-1f);
    y = fmaf(y, f,  2.0000714765e-1f);
    y = fmaf(y, f, -2.4999993993e-1f);
    y = fmaf(y, f,  3.3333331174e-1f);
    y = y * f * z;
    float ef = (float)e;
    y = fmaf(ef, -2.12194440e-4f, y);
    y = fmaf(-0.5f, z, y);
    float r = f + y;
    return fmaf(ef, 0.693359375f, r);
}

// ================= mma.sync GEMM body (unchanged from R13) ======================
__device__ void gemm_mma_body(int idx, char* smem,
                              const float* __restrict__ lat,
                              const float* __restrict__ mu,
                              const float* __restrict__ logvar) {
    int tid = threadIdx.x;
    int lane = tid & 31, wd = tid >> 5;
    int i0 = (idx >> 3) * 64;
    int j0 = (idx & 7) * 64;
    int mi = wd >> 1;
    int nj = wd & 1;

    uint32_t sbA = smem_to_u32(smem);
    uint32_t sbB = sbA + ATILE_B;

    float d[4][4];
#pragma unroll
    for (int ns = 0; ns < 4; ns++)
#pragma unroll
        for (int q = 0; q < 4; q++) d[ns][q] = 0.0f;

    int rowA = mi * 16 + (lane & 15);
    uint32_t addrA = sbA + rowA * (GROW * 2) + (lane >> 4) * 16;
    int rowB = nj * 32 + ((lane >> 4) * 8) + (lane & 7);
    uint32_t addrB0 = sbB + rowB * (GROW * 2) + ((lane >> 3) & 1) * 16;
    uint32_t addrB1 = addrB0 + 16 * (GROW * 2);

    for (int ch = 0; ch < 16; ch++) {
        bool fh = ch < 8;
        int gk0 = (ch & 7) * 32;

#pragma unroll
        for (int e = 0; e < 4; e++) {
            int q = e * 256 + tid;
            int row = q >> 4, cu = q & 15;
            float2 vl = *(const float2*)&lat[(i0 + row) * ZD + gk0 + cu * 2];
            float a0, a1;
            if (fh) { a0 = -0.5f * vl.x * vl.x; a1 = -0.5f * vl.y * vl.y; }
            else    { a0 = vl.x; a1 = vl.y; }
            *(uint32_t*)(smem + row * (GROW * 2) + cu * 4) = bf16x2_pack(a0, a1);
        }
#pragma unroll
        for (int e = 0; e < 4; e++) {
            int q = e * 256 + tid;
            int row = q >> 4, cu = q & 15;
            float2 lv = *(const float2*)&logvar[(j0 + row) * ZD + gk0 + cu * 2];
            float w0 = __expf(lv.x), w1 = __expf(lv.y);
            float b0, b1;
            if (fh) { b0 = w0; b1 = w1; }
            else {
                float2 mm = *(const float2*)&mu[(j0 + row) * ZD + gk0 + cu * 2];
                b0 = mm.x * w0; b1 = mm.y * w1;
            }
            *(uint32_t*)(smem + ATILE_B + row * (GROW * 2) + cu * 4) =
                bf16x2_pack(b0, b1);
        }
        __syncthreads();

#pragma unroll
        for (int ks = 0; ks < 2; ks++) {
            uint32_t a[4], b[8];
            ldmx4(a,     addrA  + ks * 32);
            ldmx4(b,     addrB0 + ks * 32);
            ldmx4(b + 4, addrB1 + ks * 32);
#pragma unroll
            for (int ns = 0; ns < 4; ns++)
                mma_bf16(d[ns], a, b + ns * 2);
        }
        __syncthreads();
    }

    int r0 = i0 + mi * 16 + (lane >> 2);
    int c0 = j0 + nj * 32 + (lane & 3) * 2;
#pragma unroll
    for (int ns = 0; ns < 4; ns++) {
        *(float2*)&g_M0[r0 * BSZ + c0 + ns * 8]       = make_float2(d[ns][0], d[ns][1]);
        *(float2*)&g_M0[(r0 + 8) * BSZ + c0 + ns * 8] = make_float2(d[ns][2], d[ns][3]);
    }
}

// ================= pm body: R13 base + pipe-split exp (pair 0 poly, 1..3 MUFU) ==
__device__ void pm_body(int idx, const float* __restrict__ lat,
                        const float* __restrict__ mu,
                        const float* __restrict__ logvar) {
    int jc = idx & (JCHUNKS - 1);
    int i0 = (idx >> 3) * TI;
    int t  = threadIdx.x;

    u64 s2[TI / 2], h2[TI / 2], acc[TI / 2];
#pragma unroll
    for (int p = 0; p < TI / 2; p++) {
        float v0 = lat[(i0 + 2 * p) * ZD + t];
        float v1 = lat[(i0 + 2 * p + 1) * ZD + t];
        s2[p]  = pk2(v0 * LOG2E_F, v1 * LOG2E_F);
        h2[p]  = pk2(-0.5f * v0 * v0, -0.5f * v1 * v1);
        acc[p] = 0ULL;
    }

    int jbase = jc * JC;

    for (int jg = 0; jg < JC; jg += 8) {
        uint32_t a16[TI / 2];
#pragma unroll
        for (int p = 1; p < TI / 2; p++) a16[p] = 0u;

#pragma unroll
        for (int j = 0; j < 8; j++) {
            int off = (jbase + jg + j) * ZD + t;
            float lv = logvar[off];
            float m  = mu[off];
            float w  = __expf(lv);
            float w2v = w * LOG2E_F;
            float a2v = m * w2v;
            float c2v = -0.5f * LOG2E_F * (fmaf(m * m, w, lv) + LOG2PI_F);
            u64 w2 = pk2(w2v, w2v), a2 = pk2(a2v, a2v), c2 = pk2(c2v, c2v);

            // pair 0: FMA-pipe polynomial (keeps MUFU free; phi = 1/4)
            {
                u64 x = fma2(h2[0], w2, fma2(s2[0], a2, c2));
                acc[0] = add2(acc[0], exp2_poly2(x));
            }
            // pairs 1..3: MUFU f16x2
#pragma unroll
            for (int p = 1; p < TI / 2; p++) {
                u64 x = fma2(h2[p], w2, fma2(s2[p], a2, c2));
                a16[p] = hadd2(a16[p], exp2_to_f16x2(x));
            }
        }
#pragma unroll
        for (int p = 1; p < TI / 2; p++)
            acc[p] = add2(acc[p], f16x2_to_f32x2(a16[p]));
    }

#pragma unroll
    for (int p = 0; p < TI / 2; p++) {
        float a0, a1;
        upk2(acc[p], a0, a1);
        g_S[jc][(i0 + 2 * p) * ZD + t]     = a0;
        g_S[jc][(i0 + 2 * p + 1) * ZD + t] = a1;
    }
}

// ================= rec body (unchanged) =========================================
__device__ void rec_body(int idx, const float* __restrict__ data,
                         const float* __restrict__ recon, int n4, float* sh,
                         const float* __restrict__ mu,
                         const float* __restrict__ logvar) {
    int t = threadIdx.x;

    {
        int off = idx * ZD + t;
        float lv = logvar[off];
        float m  = mu[off];
        float w  = __expf(lv);
        float c  = -0.5f * (fmaf(m * m, w, lv) + LOG2PI_F);
        float dw = fmaf(0.5f, __expf(lv + m * m), fmaf(-0.5f, lv, -0.5f));
        float cs = block_sum_256(c, sh);
        if (t == 0) g_Crow[idx] = cs;
        float ds = block_sum_256(dw, sh);
        if (t == 0) g_dwkl[idx] = ds;
    }

    const float4* d4 = (const float4*)data;
    const float4* r4 = (const float4*)recon;
    float acc = 0.0f;
    for (int i = idx * 256 + t; i < n4; i += REC_BLOCKS * 256) {
        float4 d = d4[i];
        float4 r = r4[i];
        acc += d.x * __logf(r.x) + (1.0f - d.x) * __logf(1.0f - r.x);
        acc += d.y * __logf(r.y) + (1.0f - d.y) * __logf(1.0f - r.y);
        acc += d.z * __logf(r.z) + (1.0f - d.z) * __logf(1.0f - r.z);
        acc += d.w * __logf(r.w) + (1.0f - d.w) * __logf(1.0f - r.w);
    }
    float s = block_sum_256(acc, sh);
    if (t == 0) g_recb[idx] = s;
}

// ================= kernel 1: heterogeneous mega-kernel (R13 layout) =============
// 1088 blocks, period-17 interleave: 1 gemm : 8 pm : 8 rec per group.
__global__ void __launch_bounds__(256, 4) mega_kernel(const float* __restrict__ data,
                                                      const float* __restrict__ recon,
                                                      const float* __restrict__ lat,
                                                      const float* __restrict__ mu,
                                                      const float* __restrict__ logvar,
                                                      int n4) {
    __shared__ __align__(16) char smem[SMEM_SZ];
    int bx = blockIdx.x;
    int r = bx % 17;
    int q = bx / 17;
    if (r == 0) {
        gemm_mma_body(q, smem, lat, mu, logvar);
    } else if (r <= 8) {
        pm_body(q * 8 + (r - 1), lat, mu, logvar);
    } else {
        rec_body(q * 8 + (r - 9), data, recon, n4, (float*)smem, mu, logvar);
    }
}

// ================= kernel 2: epilogue (R13 proven version) ======================
__global__ void __launch_bounds__(512) epi_kernel(float* __restrict__ out,
                                                  const void* __restrict__ dsz) {
    __shared__ float sh[16];
    __shared__ float smx;
    __shared__ bool s_last;
    int i = blockIdx.x, t = threadIdx.x;

    int   iv = ((const int*)dsz)[0];
    float fv = ((const float*)dsz)[0];
    float ds_val = (iv > 0 && iv < 1073741824) ? (float)iv : fv;
    float log_norm = logf((float)BSZ) + logf(ds_val);

    // --- logqz: LSE over j (one j per thread) ---
    float v = g_Crow[t] + g_M0[i * BSZ + t];
    float mx = block_max_512(v, sh);
    if (t == 0) smx = mx;
    __syncthreads();
    mx = smx;
    float se = block_sum_512(__expf(v - mx), sh);
    float logqz = mx + __logf(se) - log_norm;     // valid in t==0

    // --- pm: sum_k log(sum over chunks), k handled by t<256 ---
    float lg = 0.0f;
    if (t < ZD) {
        int idx = i * ZD + t;
        float S = 0.0f;
#pragma unroll
        for (int jc = 0; jc < JCHUNKS; jc++) S += g_S[jc][idx];
        lg = fast_log(S);
    }
    float tot = block_sum_512(lg, sh);

    if (t == 0) {
        float pm = tot - (float)ZD * log_norm;
        g_tc[i] = logqz - pm;
        __threadfence();
        unsigned int prev = atomicAdd(&g_ctr, 1u);
        s_last = (prev == BSZ - 1);
    }
    __syncthreads();

    if (s_last) {
        float rec = 0.0f, dw = 0.0f, tc = 0.0f;
        for (int b = t; b < REC_BLOCKS; b += 512) rec += g_recb[b];
        for (int b = t; b < BSZ; b += 512) {
            dw += g_dwkl[b];
            tc += g_tc[b];
        }
        rec = block_sum_512(rec, sh);
        dw  = block_sum_512(dw,  sh);
        tc  = block_sum_512(tc,  sh);
        if (t == 0) {
            out[0] = (tc + dw - rec) * (1.0f / (float)BSZ);
            g_ctr = 0;                 // reset for next graph replay
        }
    }
}

// ---------------- launch ----------------------------------------------------------
extern "C" void kernel_launch(void* const* d_in, const int* in_sizes, int n_in,
                              void* d_out, int out_size) {
    const float* data   = (const float*)d_in[0];
    const float* recon  = (const float*)d_in[1];
    const float* latent = (const float*)d_in[2];
    const float* mu     = (const float*)d_in[3];
    const float* logvar = (const float*)d_in[4];
    const void*  dsz    = d_in[5];

    int n4 = in_sizes[0] / 4;

    mega_kernel<<<17 * NGEMM, 256>>>(data, recon, latent, mu, logvar, n4);
    epi_kernel<<<BSZ, 512>>>((float*)d_out, dsz);
}

// round 17
// speedup vs baseline: 1.2971x; 1.2971x over previous
#include <cuda_runtime.h>
#include <math.h>
#include <stdint.h>

#define BSZ 512
#define ZD  256
#define REC_BLOCKS 512
#define TI 8                    // i-values per pm block (4 f32x2 pairs)
#define JCHUNKS 8
#define JC (BSZ / JCHUNKS)      // 64
#define NGEMM 64                // mma.sync gemm blocks (8 i-tiles x 8 j-tiles)
#define LOG2PI_F 1.8378770664093453f
#define LOG2E_F  1.4426950408889634f

// gemm smem: A[64][40] bf16 + B[64][40] bf16 (40 = 32 + 8 pad; 80B rows, 16B-mult)
#define GROW 40
#define ATILE_B (64 * GROW * 2)      // 5120
#define SMEM_SZ (2 * ATILE_B)        // 10240

typedef unsigned long long u64;

// ---------------- scratch ----------------------------------------------------
__device__ float g_Crow[BSZ];
__device__ float g_dwkl[BSZ];
__device__ float g_recb[REC_BLOCKS];
__device__ float g_tc[BSZ];
__device__ unsigned int g_ctr;               // zero-init; epi resets it each run
__device__ float g_M0[BSZ * BSZ];            // GEMM result (1MB, single slab)
__device__ float g_S[JCHUNKS][BSZ * ZD];     // pm partial sums (4MB)

// ---------------- packed helpers ----------------------------------------------
__device__ __forceinline__ u64 pk2(float lo, float hi) {
    u64 r; asm("mov.b64 %0,{%1,%2};" : "=l"(r) : "f"(lo), "f"(hi)); return r;
}
__device__ __forceinline__ void upk2(u64 v, float& lo, float& hi) {
    asm("mov.b64 {%0,%1},%2;" : "=f"(lo), "=f"(hi) : "l"(v));
}
__device__ __forceinline__ u64 fma2(u64 a, u64 b, u64 c) {
    u64 d; asm("fma.rn.f32x2 %0,%1,%2,%3;" : "=l"(d) : "l"(a), "l"(b), "l"(c)); return d;
}
__device__ __forceinline__ u64 add2(u64 a, u64 b) {
    u64 d; asm("add.rn.f32x2 %0,%1,%2;" : "=l"(d) : "l"(a), "l"(b)); return d;
}
__device__ __forceinline__ uint32_t exp2_to_f16x2(u64 x) {
    float xlo, xhi;
    upk2(x, xlo, xhi);
    uint32_t hx, he;
    asm("cvt.rn.f16x2.f32 %0,%1,%2;" : "=r"(hx) : "f"(xhi), "f"(xlo));
    asm("ex2.approx.f16x2 %0,%1;" : "=r"(he) : "r"(hx));
    return he;
}
__device__ __forceinline__ uint32_t hadd2(uint32_t a, uint32_t b) {
    uint32_t d; asm("add.rn.f16x2 %0,%1,%2;" : "=r"(d) : "r"(a), "r"(b)); return d;
}
__device__ __forceinline__ u64 f16x2_to_f32x2(uint32_t h) {
    float lo, hi;
    asm("{\n\t.reg .f16 l,h;\n\tmov.b32 {l,h},%2;\n\t"
        "cvt.f32.f16 %0,l;\n\tcvt.f32.f16 %1,h;\n\t}"
        : "=f"(lo), "=f"(hi) : "r"(h));
    return pk2(lo, hi);
}
__device__ __forceinline__ uint32_t bf16x2_pack(float lo, float hi) {
    uint32_t r; asm("cvt.rn.bf16x2.f32 %0,%1,%2;" : "=r"(r) : "f"(hi), "f"(lo)); return r;
}
__device__ __forceinline__ uint32_t smem_to_u32(const void* p) {
    uint32_t a;
    asm("{ .reg .u64 t; cvta.to.shared.u64 t, %1; cvt.u32.u64 %0, t; }"
        : "=r"(a) : "l"(p));
    return a;
}

// ---------------- mma.sync helpers (sm_80-era PTX; compute_103-safe) -----------
__device__ __forceinline__ void ldmx4(uint32_t* r, uint32_t addr) {
    asm volatile("ldmatrix.sync.aligned.m8n8.x4.shared.b16 {%0,%1,%2,%3}, [%4];"
        : "=r"(r[0]), "=r"(r[1]), "=r"(r[2]), "=r"(r[3]) : "r"(addr));
}
__device__ __forceinline__ void mma_bf16(float* d, const uint32_t* a,
                                         const uint32_t* b) {
    asm volatile("mma.sync.aligned.m16n8k16.row.col.f32.bf16.bf16.f32 "
        "{%0,%1,%2,%3}, {%4,%5,%6,%7}, {%8,%9}, {%0,%1,%2,%3};"
        : "+f"(d[0]), "+f"(d[1]), "+f"(d[2]), "+f"(d[3])
        : "r"(a[0]), "r"(a[1]), "r"(a[2]), "r"(a[3]), "r"(b[0]), "r"(b[1]));
}

// ---------------- reductions --------------------------------------------------
__device__ __forceinline__ float warp_sum(float v) {
#pragma unroll
    for (int o = 16; o; o >>= 1) v += __shfl_xor_sync(0xffffffffu, v, o);
    return v;
}
__device__ __forceinline__ float warp_max(float v) {
#pragma unroll
    for (int o = 16; o; o >>= 1) v = fmaxf(v, __shfl_xor_sync(0xffffffffu, v, o));
    return v;
}
__device__ __forceinline__ float block_sum_256(float v, float* sh) {
    int lane = threadIdx.x & 31, w = threadIdx.x >> 5;
    v = warp_sum(v);
    if (lane == 0) sh[w] = v;
    __syncthreads();
    float r = (threadIdx.x < 8) ? sh[threadIdx.x] : 0.0f;
    if (w == 0) r = warp_sum(r);
    __syncthreads();
    return r;
}

// ---------------- FMA-pipe natural log -----------------------------------------
__device__ __forceinline__ float fast_log(float x) {
    int ix = __float_as_int(x);
    int e  = (ix - 0x3f3504f3) >> 23;
    float m = __int_as_float(ix - (e << 23));
    float f = m - 1.0f;
    float z = f * f;
    float y = 7.0376836292e-2f;
    y = fmaf(y, f, -1.1514610310e-1f);
    y = fmaf(y, f,  1.1676998740e-1f);
    y = fmaf(y, f, -1.2420140846e-1f);
    y = fmaf(y, f,  1.4249322787e-1f);
    y = fmaf(y, f, -1.6668057665e-1f);
    y = fmaf(y, f,  2.0000714765e-1f);
    y = fmaf(y, f, -2.4999993993e-1f);
    y = fmaf(y, f,  3.3333331174e-1f);
    y = y * f * z;
    float ef = (float)e;
    y = fmaf(ef, -2.12194440e-4f, y);
    y = fmaf(-0.5f, z, y);
    float r = f + y;
    return fmaf(ef, 0.693359375f, r);
}

// ================= mma.sync GEMM body (unchanged from R13) ======================
__device__ void gemm_mma_body(int idx, char* smem,
                              const float* __restrict__ lat,
                              const float* __restrict__ mu,
                              const float* __restrict__ logvar) {
    int tid = threadIdx.x;
    int lane = tid & 31, wd = tid >> 5;
    int i0 = (idx >> 3) * 64;
    int j0 = (idx & 7) * 64;
    int mi = wd >> 1;
    int nj = wd & 1;

    uint32_t sbA = smem_to_u32(smem);
    uint32_t sbB = sbA + ATILE_B;

    float d[4][4];
#pragma unroll
    for (int ns = 0; ns < 4; ns++)
#pragma unroll
        for (int q = 0; q < 4; q++) d[ns][q] = 0.0f;

    int rowA = mi * 16 + (lane & 15);
    uint32_t addrA = sbA + rowA * (GROW * 2) + (lane >> 4) * 16;
    int rowB = nj * 32 + ((lane >> 4) * 8) + (lane & 7);
    uint32_t addrB0 = sbB + rowB * (GROW * 2) + ((lane >> 3) & 1) * 16;
    uint32_t addrB1 = addrB0 + 16 * (GROW * 2);

    for (int ch = 0; ch < 16; ch++) {
        bool fh = ch < 8;
        int gk0 = (ch & 7) * 32;

#pragma unroll
        for (int e = 0; e < 4; e++) {
            int q = e * 256 + tid;
            int row = q >> 4, cu = q & 15;
            float2 vl = *(const float2*)&lat[(i0 + row) * ZD + gk0 + cu * 2];
            float a0, a1;
            if (fh) { a0 = -0.5f * vl.x * vl.x; a1 = -0.5f * vl.y * vl.y; }
            else    { a0 = vl.x; a1 = vl.y; }
            *(uint32_t*)(smem + row * (GROW * 2) + cu * 4) = bf16x2_pack(a0, a1);
        }
#pragma unroll
        for (int e = 0; e < 4; e++) {
            int q = e * 256 + tid;
            int row = q >> 4, cu = q & 15;
            float2 lv = *(const float2*)&logvar[(j0 + row) * ZD + gk0 + cu * 2];
            float w0 = __expf(lv.x), w1 = __expf(lv.y);
            float b0, b1;
            if (fh) { b0 = w0; b1 = w1; }
            else {
                float2 mm = *(const float2*)&mu[(j0 + row) * ZD + gk0 + cu * 2];
                b0 = mm.x * w0; b1 = mm.y * w1;
            }
            *(uint32_t*)(smem + ATILE_B + row * (GROW * 2) + cu * 4) =
                bf16x2_pack(b0, b1);
        }
        __syncthreads();

#pragma unroll
        for (int ks = 0; ks < 2; ks++) {
            uint32_t a[4], b[8];
            ldmx4(a,     addrA  + ks * 32);
            ldmx4(b,     addrB0 + ks * 32);
            ldmx4(b + 4, addrB1 + ks * 32);
#pragma unroll
            for (int ns = 0; ns < 4; ns++)
                mma_bf16(d[ns], a, b + ns * 2);
        }
        __syncthreads();
    }

    int r0 = i0 + mi * 16 + (lane >> 2);
    int c0 = j0 + nj * 32 + (lane & 3) * 2;
#pragma unroll
    for (int ns = 0; ns < 4; ns++) {
        *(float2*)&g_M0[r0 * BSZ + c0 + ns * 8]       = make_float2(d[ns][0], d[ns][1]);
        *(float2*)&g_M0[(r0 + 8) * BSZ + c0 + ns * 8] = make_float2(d[ns][2], d[ns][3]);
    }
}

// ================= pm body (exact R13) ==========================================
__device__ void pm_body(int idx, const float* __restrict__ lat,
                        const float* __restrict__ mu,
                        const float* __restrict__ logvar) {
    int jc = idx & (JCHUNKS - 1);
    int i0 = (idx >> 3) * TI;
    int t  = threadIdx.x;

    u64 s2[TI / 2], h2[TI / 2], acc[TI / 2];
#pragma unroll
    for (int p = 0; p < TI / 2; p++) {
        float v0 = lat[(i0 + 2 * p) * ZD + t];
        float v1 = lat[(i0 + 2 * p + 1) * ZD + t];
        s2[p]  = pk2(v0 * LOG2E_F, v1 * LOG2E_F);
        h2[p]  = pk2(-0.5f * v0 * v0, -0.5f * v1 * v1);
        acc[p] = 0ULL;
    }

    int jbase = jc * JC;

    for (int jg = 0; jg < JC; jg += 8) {
        uint32_t a16[TI / 2];
#pragma unroll
        for (int p = 0; p < TI / 2; p++) a16[p] = 0u;

#pragma unroll
        for (int j = 0; j < 8; j++) {
            int off = (jbase + jg + j) * ZD + t;
            float lv = logvar[off];
            float m  = mu[off];
            float w  = __expf(lv);
            float w2v = w * LOG2E_F;
            float a2v = m * w2v;
            float c2v = -0.5f * LOG2E_F * (fmaf(m * m, w, lv) + LOG2PI_F);
            u64 w2 = pk2(w2v, w2v), a2 = pk2(a2v, a2v), c2 = pk2(c2v, c2v);

#pragma unroll
            for (int p = 0; p < TI / 2; p++) {
                u64 x = fma2(h2[p], w2, fma2(s2[p], a2, c2));
                a16[p] = hadd2(a16[p], exp2_to_f16x2(x));
            }
        }
#pragma unroll
        for (int p = 0; p < TI / 2; p++)
            acc[p] = add2(acc[p], f16x2_to_f32x2(a16[p]));
    }

#pragma unroll
    for (int p = 0; p < TI / 2; p++) {
        float a0, a1;
        upk2(acc[p], a0, a1);
        g_S[jc][(i0 + 2 * p) * ZD + t]     = a0;
        g_S[jc][(i0 + 2 * p + 1) * ZD + t] = a1;
    }
}

// ================= rec body (exact R13) =========================================
__device__ void rec_body(int idx, const float* __restrict__ data,
                         const float* __restrict__ recon, int n4, float* sh,
                         const float* __restrict__ mu,
                         const float* __restrict__ logvar) {
    int t = threadIdx.x;

    {
        int off = idx * ZD + t;
        float lv = logvar[off];
        float m  = mu[off];
        float w  = __expf(lv);
        float c  = -0.5f * (fmaf(m * m, w, lv) + LOG2PI_F);
        float dw = fmaf(0.5f, __expf(lv + m * m), fmaf(-0.5f, lv, -0.5f));
        float cs = block_sum_256(c, sh);
        if (t == 0) g_Crow[idx] = cs;
        float ds = block_sum_256(dw, sh);
        if (t == 0) g_dwkl[idx] = ds;
    }

    const float4* d4 = (const float4*)data;
    const float4* r4 = (const float4*)recon;
    float acc = 0.0f;
    for (int i = idx * 256 + t; i < n4; i += REC_BLOCKS * 256) {
        float4 d = d4[i];
        float4 r = r4[i];
        acc += d.x * __logf(r.x) + (1.0f - d.x) * __logf(1.0f - r.x);
        acc += d.y * __logf(r.y) + (1.0f - d.y) * __logf(1.0f - r.y);
        acc += d.z * __logf(r.z) + (1.0f - d.z) * __logf(1.0f - r.z);
        acc += d.w * __logf(r.w) + (1.0f - d.w) * __logf(1.0f - r.w);
    }
    float s = block_sum_256(acc, sh);
    if (t == 0) g_recb[idx] = s;
}

// ================= kernel 1: heterogeneous mega-kernel (exact R13) ==============
__global__ void __launch_bounds__(256, 4) mega_kernel(const float* __restrict__ data,
                                                      const float* __restrict__ recon,
                                                      const float* __restrict__ lat,
                                                      const float* __restrict__ mu,
                                                      const float* __restrict__ logvar,
                                                      int n4) {
    __shared__ __align__(16) char smem[SMEM_SZ];
    int bx = blockIdx.x;
    int r = bx % 17;
    int q = bx / 17;
    if (r == 0) {
        gemm_mma_body(q, smem, lat, mu, logvar);
    } else if (r <= 8) {
        pm_body(q * 8 + (r - 1), lat, mu, logvar);
    } else {
        rec_body(q * 8 + (r - 9), data, recon, n4, (float*)smem, mu, logvar);
    }
}

// ================= kernel 2: epilogue v3 — 256 thr/block (single wave) ==========
// 512 blocks x 8 warps -> 4 blocks/SM -> 592 blocks/wave -> whole grid in 1 wave.
// All loads hoisted before barriers; se & lg sums batched into one phase.
__global__ void __launch_bounds__(256) epi_kernel(float* __restrict__ out,
                                                  const void* __restrict__ dsz) {
    __shared__ float shA[8];
    __shared__ float shB[8];
    __shared__ float r_mx, r_se, r_lg;
    __shared__ bool s_last;
    int i = blockIdx.x, t = threadIdx.x;
    int lane = t & 31, w = t >> 5;

    int   iv = ((const int*)dsz)[0];
    float fv = ((const float*)dsz)[0];
    float ds_val = (iv > 0 && iv < 1073741824) ? (float)iv : fv;
    float log_norm = logf((float)BSZ) + logf(ds_val);

    // ---- hoist ALL global loads (full MLP before any barrier) ----
    float v0 = g_Crow[t]       + g_M0[i * BSZ + t];
    float v1 = g_Crow[t + 256] + g_M0[i * BSZ + t + 256];
    float S = 0.0f;
#pragma unroll
    for (int jc = 0; jc < JCHUNKS; jc++) S += g_S[jc][i * ZD + t];
    float lg = fast_log(S);

    // ---- phase 1: block max of v0,v1 ----
    float mx = warp_max(fmaxf(v0, v1));
    if (lane == 0) shA[w] = mx;
    __syncthreads();
    if (w == 0) {
        float r = (lane < 8) ? shA[lane] : -INFINITY;
        r = warp_max(r);
        if (lane == 0) r_mx = r;
    }
    __syncthreads();
    mx = r_mx;

    // ---- phase 2: batched dual sum (se on warp0 tree, lg on warp1 tree) ----
    float se = __expf(v0 - mx) + __expf(v1 - mx);
    float a = warp_sum(se);
    float b = warp_sum(lg);
    if (lane == 0) { shA[w] = a; shB[w] = b; }
    __syncthreads();
    if (w == 0) {
        float r = (lane < 8) ? shA[lane] : 0.0f;
        r = warp_sum(r);
        if (lane == 0) r_se = r;
    } else if (w == 1) {
        float r = (lane < 8) ? shB[lane] : 0.0f;
        r = warp_sum(r);
        if (lane == 0) r_lg = r;
    }
    __syncthreads();

    if (t == 0) {
        float logqz = mx + __logf(r_se) - log_norm;
        float pm    = r_lg - (float)ZD * log_norm;
        g_tc[i] = logqz - pm;
        __threadfence();
        unsigned int prev = atomicAdd(&g_ctr, 1u);
        s_last = (prev == BSZ - 1);
    }
    __syncthreads();

    if (s_last) {
        float rec = 0.0f, dw = 0.0f, tc = 0.0f;
        for (int bb = t; bb < REC_BLOCKS; bb += 256) rec += g_recb[bb];
        for (int bb = t; bb < BSZ; bb += 256) {
            dw += g_dwkl[bb];
            tc += g_tc[bb];
        }
        rec = block_sum_256(rec, shA);
        dw  = block_sum_256(dw,  shA);
        tc  = block_sum_256(tc,  shA);
        if (t == 0) {
            out[0] = (tc + dw - rec) * (1.0f / (float)BSZ);
            g_ctr = 0;                 // reset for next graph replay
        }
    }
}

// ---------------- launch ----------------------------------------------------------
extern "C" void kernel_launch(void* const* d_in, const int* in_sizes, int n_in,
                              void* d_out, int out_size) {
    const float* data   = (const float*)d_in[0];
    const float* recon  = (const float*)d_in[1];
    const float* latent = (const float*)d_in[2];
    const float* mu     = (const float*)d_in[3];
    const float* logvar = (const float*)d_in[4];
    const void*  dsz    = d_in[5];

    int n4 = in_sizes[0] / 4;

    mega_kernel<<<17 * NGEMM, 256>>>(data, recon, latent, mu, logvar, n4);
    epi_kernel<<<BSZ, 256>>>((float*)d_out, dsz);
}